// round 2
// baseline (speedup 1.0000x reference)
#include <cuda_runtime.h>

#define S     2048
#define H     16
#define D     64
#define HID   1024
#define KHH   204
#define LCOMP 512
#define KC    716     // KHH + LCOMP
#define KCP   720     // padded score row
#define SCALE 0.125f  // 1/sqrt(64)

// ---------------- device scratch (allocation-free; module globals) ----------------
__device__ float g_q[S * HID];
__device__ float g_k[S * HID];
__device__ float g_v[S * HID];
__device__ float g_ao[S * HID];
__device__ float g_scores[(size_t)H * S * S];   // raw scaled scores (256 MB)
__device__ float g_rowM[H * S];
__device__ float g_rowZ[H * S];                 // 1/Z
__device__ float g_ent[H * S];
__device__ float g_maxa[H * S];
__device__ float g_infl[H * S];
__device__ float g_imp[S];
__device__ int   g_hhidx[KHH];
__device__ float g_kcat[(size_t)H * KC * D];
__device__ float g_vcat[(size_t)H * KC * D];

// ---------------- generic 128x128x8 SGEMM body (M=2048 rows, N=K=1024) ----------------
__device__ __forceinline__ void sgemm_body(const float* __restrict__ A,
                                           const float* __restrict__ B,
                                           float* __restrict__ C) {
    const int Kdim = 1024, N = 1024;
    __shared__ float As[8][128];
    __shared__ float Bs[8][128];
    int tid  = threadIdx.x;
    int crow = blockIdx.y * 128;
    int ccol = blockIdx.x * 128;
    int aRow = tid >> 1;
    int aCol = (tid & 1) * 4;
    int bRow = tid >> 5;
    int bCol = (tid & 31) * 4;
    int tRow = (tid >> 4) * 8;
    int tCol = (tid & 15) * 8;
    float acc[8][8];
#pragma unroll
    for (int i = 0; i < 8; i++)
#pragma unroll
        for (int j = 0; j < 8; j++) acc[i][j] = 0.0f;

    for (int k0 = 0; k0 < Kdim; k0 += 8) {
        float4 av = *(const float4*)&A[(size_t)(crow + aRow) * Kdim + k0 + aCol];
        As[aCol + 0][aRow] = av.x;
        As[aCol + 1][aRow] = av.y;
        As[aCol + 2][aRow] = av.z;
        As[aCol + 3][aRow] = av.w;
        *(float4*)&Bs[bRow][bCol] =
            *(const float4*)&B[(size_t)(k0 + bRow) * N + ccol + bCol];
        __syncthreads();
#pragma unroll
        for (int kk = 0; kk < 8; kk++) {
            float rm[8], rn[8];
            *(float4*)&rm[0] = *(float4*)&As[kk][tRow];
            *(float4*)&rm[4] = *(float4*)&As[kk][tRow + 4];
            *(float4*)&rn[0] = *(float4*)&Bs[kk][tCol];
            *(float4*)&rn[4] = *(float4*)&Bs[kk][tCol + 4];
#pragma unroll
            for (int i = 0; i < 8; i++)
#pragma unroll
                for (int j = 0; j < 8; j++) acc[i][j] += rm[i] * rn[j];
        }
        __syncthreads();
    }
#pragma unroll
    for (int i = 0; i < 8; i++)
#pragma unroll
        for (int j = 0; j < 8; j += 4) {
            float4 o = make_float4(acc[i][j], acc[i][j + 1], acc[i][j + 2], acc[i][j + 3]);
            *(float4*)&C[(size_t)(crow + tRow + i) * N + ccol + tCol + j] = o;
        }
}

__global__ __launch_bounds__(256) void qkv_kernel(const float* __restrict__ x,
                                                  const float* __restrict__ wq,
                                                  const float* __restrict__ wk,
                                                  const float* __restrict__ wv) {
    const float* B = blockIdx.z == 0 ? wq : (blockIdx.z == 1 ? wk : wv);
    float* C = blockIdx.z == 0 ? g_q : (blockIdx.z == 1 ? g_k : g_v);
    sgemm_body(x, B, C);
}

__global__ __launch_bounds__(256) void out_kernel(const float* __restrict__ wo,
                                                  float* __restrict__ out) {
    sgemm_body(g_ao, wo, out);
}

// ---------------- scores GEMM: scores[h] = scale * Q_h @ K_h^T ----------------
__global__ __launch_bounds__(256) void scores_kernel() {
    int h  = blockIdx.z;
    int q0 = blockIdx.y * 64;
    int k0 = blockIdx.x * 64;
    __shared__ float Qs[64 * 68];  // [d][row]
    __shared__ float Ks[64 * 68];  // [d][col]
    int tid = threadIdx.x;
    for (int f = tid; f < 1024; f += 256) {
        int r = f >> 4;
        int c = (f & 15) << 2;
        float4 qv = *(const float4*)&g_q[(size_t)(q0 + r) * HID + h * D + c];
        Qs[(c + 0) * 68 + r] = qv.x; Qs[(c + 1) * 68 + r] = qv.y;
        Qs[(c + 2) * 68 + r] = qv.z; Qs[(c + 3) * 68 + r] = qv.w;
        float4 kv = *(const float4*)&g_k[(size_t)(k0 + r) * HID + h * D + c];
        Ks[(c + 0) * 68 + r] = kv.x; Ks[(c + 1) * 68 + r] = kv.y;
        Ks[(c + 2) * 68 + r] = kv.z; Ks[(c + 3) * 68 + r] = kv.w;
    }
    __syncthreads();
    int tRow = (tid >> 4) << 2;
    int tCol = (tid & 15) << 2;
    float acc[4][4];
#pragma unroll
    for (int i = 0; i < 4; i++)
#pragma unroll
        for (int j = 0; j < 4; j++) acc[i][j] = 0.0f;
#pragma unroll 16
    for (int kk = 0; kk < 64; kk++) {
        float rm[4], rn[4];
        *(float4*)&rm[0] = *(float4*)&Qs[kk * 68 + tRow];
        *(float4*)&rn[0] = *(float4*)&Ks[kk * 68 + tCol];
#pragma unroll
        for (int i = 0; i < 4; i++)
#pragma unroll
            for (int j = 0; j < 4; j++) acc[i][j] += rm[i] * rn[j];
    }
    float* sc = g_scores + (size_t)h * S * S;
#pragma unroll
    for (int i = 0; i < 4; i++) {
        float4 o = make_float4(acc[i][0] * SCALE, acc[i][1] * SCALE,
                               acc[i][2] * SCALE, acc[i][3] * SCALE);
        *(float4*)&sc[(size_t)(q0 + tRow + i) * S + k0 + tCol] = o;
    }
}

// ---------------- per-row softmax stats: m, 1/Z, clipped entropy, max_attn ----------------
__global__ __launch_bounds__(256) void rowstats_kernel() {
    int row = blockIdx.x;  // h*S + q
    const float* sr = g_scores + (size_t)row * S;
    __shared__ float sv[S];
    __shared__ float red[256];
    int tid = threadIdx.x;

    float lm = -1e30f;
    for (int i = tid; i < S; i += 256) { float xv = sr[i]; sv[i] = xv; lm = fmaxf(lm, xv); }
    red[tid] = lm; __syncthreads();
    for (int o = 128; o; o >>= 1) { if (tid < o) red[tid] = fmaxf(red[tid], red[tid + o]); __syncthreads(); }
    float m = red[0]; __syncthreads();

    float lz = 0.f;
    for (int i = tid; i < S; i += 256) lz += __expf(sv[i] - m);
    red[tid] = lz; __syncthreads();
    for (int o = 128; o; o >>= 1) { if (tid < o) red[tid] += red[tid + o]; __syncthreads(); }
    float Z = red[0]; __syncthreads();
    float rz = 1.0f / Z;
    float logZ = __logf(Z);

    float lent = 0.f;
    for (int i = tid; i < S; i += 256) {
        float sm = sv[i] - m;
        float p = __expf(sm) * rz;
        float lp = (p >= 1e-8f) ? (sm - logZ) : -18.420680743952367f; // log(1e-8)
        lent += p * lp;
    }
    red[tid] = lent; __syncthreads();
    for (int o = 128; o; o >>= 1) { if (tid < o) red[tid] += red[tid + o]; __syncthreads(); }
    if (tid == 0) {
        g_ent[row]  = -red[0];
        g_maxa[row] = rz;   // max softmax prob = exp(m-m)/Z
        g_rowM[row] = m;
        g_rowZ[row] = rz;
    }
}

// ---------------- influence: column sums of softmax probs ----------------
__global__ __launch_bounds__(256) void influence_kernel() {
    int h = blockIdx.y;
    int j = blockIdx.x * 256 + threadIdx.x;
    __shared__ float smM[S];
    __shared__ float smZ[S];
    for (int i = threadIdx.x; i < S; i += 256) {
        smM[i] = g_rowM[h * S + i];
        smZ[i] = g_rowZ[h * S + i];
    }
    __syncthreads();
    const float* base = g_scores + (size_t)h * S * S + j;
    float acc = 0.f;
#pragma unroll 4
    for (int q = 0; q < S; q++)
        acc += __expf(base[(size_t)q * S] - smM[q]) * smZ[q];
    g_infl[h * S + j] = acc;
}

__global__ void importance_kernel() {
    int s = blockIdx.x * 256 + threadIdx.x;
    if (s >= S) return;
    float a = 0.f;
    for (int h = 0; h < H; h++)
        a += -0.4f * g_ent[h * S + s] + 0.3f * g_maxa[h * S + s] + 0.3f * g_infl[h * S + s];
    g_imp[s] = a * (1.0f / H);
}

// ---------------- top-204 via rank counting (attention is permutation invariant over keys) ----------------
__global__ void topk_kernel() {
    int i = blockIdx.x * 256 + threadIdx.x;
    if (i >= S) return;
    float vi = g_imp[i];
    int r = 0;
    for (int j = 0; j < S; j++) {
        float vj = g_imp[j];
        r += (vj > vi) || (vj == vi && j < i);
    }
    if (r < KHH) g_hhidx[r] = i;
}

// ---------------- norm-softmax-weighted 4:1 compression of K/V ----------------
__global__ __launch_bounds__(256) void compress_kernel() {
    int h = blockIdx.x;
    int which = blockIdx.y;
    const float* src = which ? g_v : g_k;
    float* dst = (which ? g_vcat : g_kcat) + ((size_t)h * KC + KHH) * D;
    __shared__ float w[S];
    __shared__ float gs[LCOMP];
    __shared__ float red[256];
    int tid = threadIdx.x;

    for (int s = tid; s < S; s += 256) {
        const float* rp = src + (size_t)s * HID + h * D;
        float a = 0.f;
#pragma unroll
        for (int dd = 0; dd < 64; dd += 4) {
            float4 xv = *(const float4*)&rp[dd];
            a += xv.x * xv.x + xv.y * xv.y + xv.z * xv.z + xv.w * xv.w;
        }
        w[s] = sqrtf(a);
    }
    __syncthreads();
    float lm = -1e30f;
    for (int s = tid; s < S; s += 256) lm = fmaxf(lm, w[s]);
    red[tid] = lm; __syncthreads();
    for (int o = 128; o; o >>= 1) { if (tid < o) red[tid] = fmaxf(red[tid], red[tid + o]); __syncthreads(); }
    float m = red[0]; __syncthreads();
    float lz = 0.f;
    for (int s = tid; s < S; s += 256) { float e = __expf(w[s] - m); w[s] = e; lz += e; }
    red[tid] = lz; __syncthreads();
    for (int o = 128; o; o >>= 1) { if (tid < o) red[tid] += red[tid + o]; __syncthreads(); }
    float rz = 1.0f / red[0]; __syncthreads();
    for (int s = tid; s < S; s += 256) w[s] *= rz;
    __syncthreads();
    for (int l = tid; l < LCOMP; l += 256)
        gs[l] = w[4 * l] + w[4 * l + 1] + w[4 * l + 2] + w[4 * l + 3];
    __syncthreads();
    for (int idx = tid; idx < LCOMP * D; idx += 256) {
        int l  = idx >> 6;
        int dd = idx & 63;
        const float* rp = src + (size_t)(4 * l) * HID + h * D + dd;
        float num = w[4 * l] * rp[0] + w[4 * l + 1] * rp[HID] +
                    w[4 * l + 2] * rp[2 * HID] + w[4 * l + 3] * rp[3 * HID];
        dst[(size_t)l * D + dd] = num / (gs[l] + 1e-8f);
    }
}

__global__ void gather_kernel() {
    int idx = blockIdx.x * 256 + threadIdx.x;
    if (idx >= H * KHH * D) return;
    int d = idx & 63;
    int i = (idx >> 6) % KHH;
    int h = idx / (KHH * D);
    int s = g_hhidx[i];
    g_kcat[((size_t)h * KC + i) * D + d] = g_k[(size_t)s * HID + h * D + d];
    g_vcat[((size_t)h * KC + i) * D + d] = g_v[(size_t)s * HID + h * D + d];
}

// ---------------- fused attention over 716 concatenated keys (16 queries / block) ----------------
__global__ __launch_bounds__(256) void attn2_kernel() {
    extern __shared__ float sm[];
    float* Qs  = sm;                       // 16*64
    float* Ss  = sm + 16 * 64;             // 16*KCP
    float* KVs = sm + 16 * 64 + 16 * KCP;  // 64*68
    int h   = blockIdx.y;
    int q0  = blockIdx.x * 16;
    int tid = threadIdx.x;
    {
        int r = tid >> 4;
        int c = (tid & 15) << 2;
        *(float4*)&Qs[r * 64 + c] =
            *(const float4*)&g_q[(size_t)(q0 + r) * HID + h * D + c];
    }
    __syncthreads();
    const float* kbase = g_kcat + (size_t)h * KC * D;
    const float* vbase = g_vcat + (size_t)h * KC * D;

    // ---- scores: Ss[16][716] ----
    int kj  = tid & 63;
    int qi0 = (tid >> 6) * 4;
    for (int kt = 0; kt < KC; kt += 64) {
        int rows = min(64, KC - kt);
        for (int f = tid; f < rows * 16; f += 256) {
            int r = f >> 4;
            int c = (f & 15) << 2;
            *(float4*)&KVs[r * 68 + c] =
                *(const float4*)&kbase[(size_t)(kt + r) * D + c];
        }
        __syncthreads();
        if (kj < rows) {
            float a0 = 0.f, a1 = 0.f, a2 = 0.f, a3 = 0.f;
#pragma unroll
            for (int dd = 0; dd < 64; dd += 4) {
                float4 kv = *(float4*)&KVs[kj * 68 + dd];
                float4 q0v = *(float4*)&Qs[(qi0 + 0) * 64 + dd];
                float4 q1v = *(float4*)&Qs[(qi0 + 1) * 64 + dd];
                float4 q2v = *(float4*)&Qs[(qi0 + 2) * 64 + dd];
                float4 q3v = *(float4*)&Qs[(qi0 + 3) * 64 + dd];
                a0 += q0v.x * kv.x + q0v.y * kv.y + q0v.z * kv.z + q0v.w * kv.w;
                a1 += q1v.x * kv.x + q1v.y * kv.y + q1v.z * kv.z + q1v.w * kv.w;
                a2 += q2v.x * kv.x + q2v.y * kv.y + q2v.z * kv.z + q2v.w * kv.w;
                a3 += q3v.x * kv.x + q3v.y * kv.y + q3v.z * kv.z + q3v.w * kv.w;
            }
            Ss[(qi0 + 0) * KCP + kt + kj] = a0 * SCALE;
            Ss[(qi0 + 1) * KCP + kt + kj] = a1 * SCALE;
            Ss[(qi0 + 2) * KCP + kt + kj] = a2 * SCALE;
            Ss[(qi0 + 3) * KCP + kt + kj] = a3 * SCALE;
        }
        __syncthreads();
    }

    // ---- softmax rows (8 warps x 2 rows) ----
    int wid = tid >> 5, lane = tid & 31;
    for (int rr = 0; rr < 2; rr++) {
        int row = wid * 2 + rr;
        float* srow = Ss + row * KCP;
        float m = -1e30f;
        for (int j = lane; j < KC; j += 32) m = fmaxf(m, srow[j]);
#pragma unroll
        for (int o = 16; o; o >>= 1) m = fmaxf(m, __shfl_xor_sync(0xffffffffu, m, o));
        float z = 0.f;
        for (int j = lane; j < KC; j += 32) { float e = __expf(srow[j] - m); srow[j] = e; z += e; }
#pragma unroll
        for (int o = 16; o; o >>= 1) z += __shfl_xor_sync(0xffffffffu, z, o);
        float rzz = 1.0f / z;
        for (int j = lane; j < KC; j += 32) srow[j] *= rzz;
    }

    // ---- P @ V ----
    int d  = tid & 63;
    int qg = tid >> 6;  // owns rows qg, qg+4, qg+8, qg+12
    float acc0 = 0.f, acc1 = 0.f, acc2 = 0.f, acc3 = 0.f;
    for (int vt = 0; vt < KC; vt += 64) {
        int rows = min(64, KC - vt);
        __syncthreads();
        for (int f = tid; f < rows * 16; f += 256) {
            int r = f >> 4;
            int c = (f & 15) << 2;
            *(float4*)&KVs[r * 68 + c] =
                *(const float4*)&vbase[(size_t)(vt + r) * D + c];
        }
        __syncthreads();
        for (int r = 0; r < rows; r += 4) {
            float v0 = KVs[(r + 0) * 68 + d];
            float v1 = KVs[(r + 1) * 68 + d];
            float v2 = KVs[(r + 2) * 68 + d];
            float v3 = KVs[(r + 3) * 68 + d];
            float4 p0 = *(float4*)&Ss[(qg + 0) * KCP + vt + r];
            float4 p1 = *(float4*)&Ss[(qg + 4) * KCP + vt + r];
            float4 p2 = *(float4*)&Ss[(qg + 8) * KCP + vt + r];
            float4 p3 = *(float4*)&Ss[(qg + 12) * KCP + vt + r];
            acc0 += p0.x * v0 + p0.y * v1 + p0.z * v2 + p0.w * v3;
            acc1 += p1.x * v0 + p1.y * v1 + p1.z * v2 + p1.w * v3;
            acc2 += p2.x * v0 + p2.y * v1 + p2.z * v2 + p2.w * v3;
            acc3 += p3.x * v0 + p3.y * v1 + p3.z * v2 + p3.w * v3;
        }
    }
    g_ao[(size_t)(q0 + qg +  0) * HID + h * D + d] = acc0;
    g_ao[(size_t)(q0 + qg +  4) * HID + h * D + d] = acc1;
    g_ao[(size_t)(q0 + qg +  8) * HID + h * D + d] = acc2;
    g_ao[(size_t)(q0 + qg + 12) * HID + h * D + d] = acc3;
}

// ---------------- host ----------------
extern "C" void kernel_launch(void* const* d_in, const int* in_sizes, int n_in,
                              void* d_out, int out_size) {
    const float* x  = (const float*)d_in[0];
    const float* wq = (const float*)d_in[1];
    const float* wk = (const float*)d_in[2];
    const float* wv = (const float*)d_in[3];
    const float* wo = (const float*)d_in[4];
    float* out = (float*)d_out;

    static bool attr_set = false;
    if (!attr_set) {
        cudaFuncSetAttribute(attn2_kernel,
                             cudaFuncAttributeMaxDynamicSharedMemorySize,
                             (16 * 64 + 16 * KCP + 64 * 68) * sizeof(float));
        attr_set = true;
    }

    qkv_kernel<<<dim3(8, 16, 3), 256>>>(x, wq, wk, wv);
    scores_kernel<<<dim3(32, 32, 16), 256>>>();
    rowstats_kernel<<<H * S, 256>>>();
    influence_kernel<<<dim3(8, 16), 256>>>();
    importance_kernel<<<8, 256>>>();
    topk_kernel<<<8, 256>>>();
    compress_kernel<<<dim3(16, 2), 256>>>();
    gather_kernel<<<(H * KHH * D + 255) / 256, 256>>>();
    attn2_kernel<<<dim3(S / 16, H), 256,
                   (16 * 64 + 16 * KCP + 64 * 68) * sizeof(float)>>>();
    out_kernel<<<dim3(8, 16), 256>>>(wo, out);
}

// round 3
// speedup vs baseline: 1.2864x; 1.2864x over previous
#include <cuda_runtime.h>

#define S     2048
#define H     16
#define D     64
#define HID   1024
#define KHH   204
#define LCOMP 512
#define KC    716     // KHH + LCOMP
#define KCP   720     // padded score row
#define SCALE 0.125f  // 1/sqrt(64)
#define NKT   32      // 64-wide k tiles per row
#define LOG1EM8 -18.420680743952367f

// ---------------- device scratch (allocation-free; module globals) ----------------
__device__ float g_q[S * HID];
__device__ float g_k[S * HID];
__device__ float g_v[S * HID];
__device__ float g_ao[S * HID];
__device__ float g_scores[(size_t)H * S * S];   // raw scaled scores (256 MB)
__device__ float g_pm[H * S * NKT];             // per-tile row max
__device__ float g_pz[H * S * NKT];             // per-tile row sumexp
__device__ float g_rowM[H * S];
__device__ float g_rowZ[H * S];                 // 1/Z
__device__ float g_logZ[H * S];
__device__ float g_ent[H * S];                  // accumulates sum p*log(clip(p)) = -entropy
__device__ float g_maxa[H * S];
__device__ float g_infl[H * S];
__device__ float g_imp[S];
__device__ int   g_hhidx[KHH];
__device__ float g_kcat[(size_t)H * KC * D];
__device__ float g_vcat[(size_t)H * KC * D];

// ---------------- generic 128x128x8 SGEMM body (M=2048 rows, N=K=1024) ----------------
__device__ __forceinline__ void sgemm_body(const float* __restrict__ A,
                                           const float* __restrict__ B,
                                           float* __restrict__ C) {
    const int Kdim = 1024, N = 1024;
    __shared__ float As[8][128];
    __shared__ float Bs[8][128];
    int tid  = threadIdx.x;
    int crow = blockIdx.y * 128;
    int ccol = blockIdx.x * 128;
    int aRow = tid >> 1;
    int aCol = (tid & 1) * 4;
    int bRow = tid >> 5;
    int bCol = (tid & 31) * 4;
    int tRow = (tid >> 4) * 8;
    int tCol = (tid & 15) * 8;
    float acc[8][8];
#pragma unroll
    for (int i = 0; i < 8; i++)
#pragma unroll
        for (int j = 0; j < 8; j++) acc[i][j] = 0.0f;

    for (int k0 = 0; k0 < Kdim; k0 += 8) {
        float4 av = *(const float4*)&A[(size_t)(crow + aRow) * Kdim + k0 + aCol];
        As[aCol + 0][aRow] = av.x;
        As[aCol + 1][aRow] = av.y;
        As[aCol + 2][aRow] = av.z;
        As[aCol + 3][aRow] = av.w;
        *(float4*)&Bs[bRow][bCol] =
            *(const float4*)&B[(size_t)(k0 + bRow) * N + ccol + bCol];
        __syncthreads();
#pragma unroll
        for (int kk = 0; kk < 8; kk++) {
            float rm[8], rn[8];
            *(float4*)&rm[0] = *(float4*)&As[kk][tRow];
            *(float4*)&rm[4] = *(float4*)&As[kk][tRow + 4];
            *(float4*)&rn[0] = *(float4*)&Bs[kk][tCol];
            *(float4*)&rn[4] = *(float4*)&Bs[kk][tCol + 4];
#pragma unroll
            for (int i = 0; i < 8; i++)
#pragma unroll
                for (int j = 0; j < 8; j++) acc[i][j] += rm[i] * rn[j];
        }
        __syncthreads();
    }
#pragma unroll
    for (int i = 0; i < 8; i++)
#pragma unroll
        for (int j = 0; j < 8; j += 4) {
            float4 o = make_float4(acc[i][j], acc[i][j + 1], acc[i][j + 2], acc[i][j + 3]);
            *(float4*)&C[(size_t)(crow + tRow + i) * N + ccol + tCol + j] = o;
        }
}

__global__ __launch_bounds__(256) void qkv_kernel(const float* __restrict__ x,
                                                  const float* __restrict__ wq,
                                                  const float* __restrict__ wk,
                                                  const float* __restrict__ wv) {
    const float* B = blockIdx.z == 0 ? wq : (blockIdx.z == 1 ? wk : wv);
    float* C = blockIdx.z == 0 ? g_q : (blockIdx.z == 1 ? g_k : g_v);
    sgemm_body(x, B, C);
}

__global__ __launch_bounds__(256) void out_kernel(const float* __restrict__ wo,
                                                  float* __restrict__ out) {
    sgemm_body(g_ao, wo, out);
}

// ---------------- scores GEMM + per-tile row max / sumexp partials ----------------
__global__ __launch_bounds__(256) void scores_kernel() {
    int h  = blockIdx.z;
    int q0 = blockIdx.y * 64;
    int k0 = blockIdx.x * 64;
    __shared__ float Qs[64 * 68];  // [d][row]
    __shared__ float Ks[64 * 68];  // [d][col]
    __shared__ float prs[64][17];
    __shared__ float tmax[64];
    int tid = threadIdx.x;
    for (int f = tid; f < 1024; f += 256) {
        int r = f >> 4;
        int c = (f & 15) << 2;
        float4 qv = *(const float4*)&g_q[(size_t)(q0 + r) * HID + h * D + c];
        Qs[(c + 0) * 68 + r] = qv.x; Qs[(c + 1) * 68 + r] = qv.y;
        Qs[(c + 2) * 68 + r] = qv.z; Qs[(c + 3) * 68 + r] = qv.w;
        float4 kv = *(const float4*)&g_k[(size_t)(k0 + r) * HID + h * D + c];
        Ks[(c + 0) * 68 + r] = kv.x; Ks[(c + 1) * 68 + r] = kv.y;
        Ks[(c + 2) * 68 + r] = kv.z; Ks[(c + 3) * 68 + r] = kv.w;
    }
    __syncthreads();
    int tRow = (tid >> 4) << 2;
    int cg   = tid & 15;
    int tCol = cg << 2;
    float acc[4][4];
#pragma unroll
    for (int i = 0; i < 4; i++)
#pragma unroll
        for (int j = 0; j < 4; j++) acc[i][j] = 0.0f;
#pragma unroll 16
    for (int kk = 0; kk < 64; kk++) {
        float rm[4], rn[4];
        *(float4*)&rm[0] = *(float4*)&Qs[kk * 68 + tRow];
        *(float4*)&rn[0] = *(float4*)&Ks[kk * 68 + tCol];
#pragma unroll
        for (int i = 0; i < 4; i++)
#pragma unroll
            for (int j = 0; j < 4; j++) acc[i][j] += rm[i] * rn[j];
    }
#pragma unroll
    for (int i = 0; i < 4; i++)
#pragma unroll
        for (int j = 0; j < 4; j++) acc[i][j] *= SCALE;

    float* sc = g_scores + (size_t)h * S * S;
#pragma unroll
    for (int i = 0; i < 4; i++) {
        float4 o = make_float4(acc[i][0], acc[i][1], acc[i][2], acc[i][3]);
        *(float4*)&sc[(size_t)(q0 + tRow + i) * S + k0 + tCol] = o;
    }

    // ---- per-tile row stats ----
#pragma unroll
    for (int i = 0; i < 4; i++)
        prs[tRow + i][cg] = fmaxf(fmaxf(acc[i][0], acc[i][1]),
                                  fmaxf(acc[i][2], acc[i][3]));
    __syncthreads();
    if (tid < 64) {
        float m = prs[tid][0];
#pragma unroll
        for (int c = 1; c < 16; c++) m = fmaxf(m, prs[tid][c]);
        tmax[tid] = m;
    }
    __syncthreads();
#pragma unroll
    for (int i = 0; i < 4; i++) {
        float m = tmax[tRow + i];
        prs[tRow + i][cg] = __expf(acc[i][0] - m) + __expf(acc[i][1] - m) +
                            __expf(acc[i][2] - m) + __expf(acc[i][3] - m);
    }
    __syncthreads();
    if (tid < 64) {
        float z = 0.f;
#pragma unroll
        for (int c = 0; c < 16; c++) z += prs[tid][c];
        size_t idx = (size_t)(h * S + q0 + tid) * NKT + blockIdx.x;
        g_pm[idx] = tmax[tid];
        g_pz[idx] = z;
    }
}

// ---------------- combine partials: m, 1/Z, logZ, max_attn ----------------
__global__ __launch_bounds__(256) void combine_kernel() {
    int row  = blockIdx.x * 8 + (threadIdx.x >> 5);  // 0..H*S-1
    int lane = threadIdx.x & 31;
    float pm = g_pm[(size_t)row * NKT + lane];
    float pz = g_pz[(size_t)row * NKT + lane];
    float m = pm;
#pragma unroll
    for (int o = 16; o; o >>= 1) m = fmaxf(m, __shfl_xor_sync(0xffffffffu, m, o));
    float z = __expf(pm - m) * pz;
#pragma unroll
    for (int o = 16; o; o >>= 1) z += __shfl_xor_sync(0xffffffffu, z, o);
    if (lane == 0) {
        float rz = 1.0f / z;
        g_rowM[row] = m;
        g_rowZ[row] = rz;
        g_logZ[row] = __logf(z);
        g_maxa[row] = rz;
    }
}

// ---------------- fused entropy + influence: single pass over scores ----------------
__global__ __launch_bounds__(256) void stats_kernel() {
    int h  = blockIdx.z;
    int q0 = blockIdx.y * 128;
    int k0 = blockIdx.x * 128;
    int tid = threadIdx.x;
    int wid = tid >> 5, lane = tid & 31;
    __shared__ float wcol[8][128];

    const float* sc = g_scores + (size_t)h * S * S;
    float c0 = 0.f, c1 = 0.f, c2 = 0.f, c3 = 0.f;

#pragma unroll 4
    for (int r = 0; r < 16; r++) {
        int row = q0 + wid * 16 + r;
        float m  = g_rowM[h * S + row];
        float rz = g_rowZ[h * S + row];
        float lz = g_logZ[h * S + row];
        float4 v = *(const float4*)&sc[(size_t)row * S + k0 + lane * 4];
        float s0 = v.x - m, s1 = v.y - m, s2 = v.z - m, s3 = v.w - m;
        float p0 = __expf(s0) * rz, p1 = __expf(s1) * rz;
        float p2 = __expf(s2) * rz, p3 = __expf(s3) * rz;
        c0 += p0; c1 += p1; c2 += p2; c3 += p3;
        float t0 = p0 * ((p0 >= 1e-8f) ? (s0 - lz) : LOG1EM8);
        float t1 = p1 * ((p1 >= 1e-8f) ? (s1 - lz) : LOG1EM8);
        float t2 = p2 * ((p2 >= 1e-8f) ? (s2 - lz) : LOG1EM8);
        float t3 = p3 * ((p3 >= 1e-8f) ? (s3 - lz) : LOG1EM8);
        float e = t0 + t1 + t2 + t3;
#pragma unroll
        for (int o = 16; o; o >>= 1) e += __shfl_xor_sync(0xffffffffu, e, o);
        if (lane == 0) atomicAdd(&g_ent[h * S + row], e);
    }
    *(float4*)&wcol[wid][lane * 4] = make_float4(c0, c1, c2, c3);
    __syncthreads();
    if (tid < 128) {
        float s = 0.f;
#pragma unroll
        for (int w = 0; w < 8; w++) s += wcol[w][tid];
        atomicAdd(&g_infl[h * S + k0 + tid], s);
    }
}

__global__ void importance_kernel() {
    int s = blockIdx.x * 256 + threadIdx.x;
    if (s >= S) return;
    float a = 0.f;
    for (int h = 0; h < H; h++)
        a += 0.4f * g_ent[h * S + s]   // g_ent = sum p log p = -entropy
           + 0.3f * g_maxa[h * S + s] + 0.3f * g_infl[h * S + s];
    g_imp[s] = a * (1.0f / H);
}

// ---------------- top-204 via rank counting (attention is permutation invariant over keys) ----------------
__global__ void topk_kernel() {
    int i = blockIdx.x * 256 + threadIdx.x;
    if (i >= S) return;
    float vi = g_imp[i];
    int r = 0;
    for (int j = 0; j < S; j++) {
        float vj = g_imp[j];
        r += (vj > vi) || (vj == vi && j < i);
    }
    if (r < KHH) g_hhidx[r] = i;
}

// ---------------- norm-softmax-weighted 4:1 compression of K/V ----------------
__global__ __launch_bounds__(256) void compress_kernel() {
    int h = blockIdx.x;
    int which = blockIdx.y;
    const float* src = which ? g_v : g_k;
    float* dst = (which ? g_vcat : g_kcat) + ((size_t)h * KC + KHH) * D;
    __shared__ float w[S];
    __shared__ float gs[LCOMP];
    __shared__ float red[256];
    int tid = threadIdx.x;

    for (int s = tid; s < S; s += 256) {
        const float* rp = src + (size_t)s * HID + h * D;
        float a = 0.f;
#pragma unroll
        for (int dd = 0; dd < 64; dd += 4) {
            float4 xv = *(const float4*)&rp[dd];
            a += xv.x * xv.x + xv.y * xv.y + xv.z * xv.z + xv.w * xv.w;
        }
        w[s] = sqrtf(a);
    }
    __syncthreads();
    float lm = -1e30f;
    for (int s = tid; s < S; s += 256) lm = fmaxf(lm, w[s]);
    red[tid] = lm; __syncthreads();
    for (int o = 128; o; o >>= 1) { if (tid < o) red[tid] = fmaxf(red[tid], red[tid + o]); __syncthreads(); }
    float m = red[0]; __syncthreads();
    float lz = 0.f;
    for (int s = tid; s < S; s += 256) { float e = __expf(w[s] - m); w[s] = e; lz += e; }
    red[tid] = lz; __syncthreads();
    for (int o = 128; o; o >>= 1) { if (tid < o) red[tid] += red[tid + o]; __syncthreads(); }
    float rz = 1.0f / red[0]; __syncthreads();
    for (int s = tid; s < S; s += 256) w[s] *= rz;
    __syncthreads();
    for (int l = tid; l < LCOMP; l += 256)
        gs[l] = w[4 * l] + w[4 * l + 1] + w[4 * l + 2] + w[4 * l + 3];
    __syncthreads();
    for (int idx = tid; idx < LCOMP * D; idx += 256) {
        int l  = idx >> 6;
        int dd = idx & 63;
        const float* rp = src + (size_t)(4 * l) * HID + h * D + dd;
        float num = w[4 * l] * rp[0] + w[4 * l + 1] * rp[HID] +
                    w[4 * l + 2] * rp[2 * HID] + w[4 * l + 3] * rp[3 * HID];
        dst[(size_t)l * D + dd] = num / (gs[l] + 1e-8f);
    }
}

__global__ void gather_kernel() {
    int idx = blockIdx.x * 256 + threadIdx.x;
    if (idx >= H * KHH * D) return;
    int d = idx & 63;
    int i = (idx >> 6) % KHH;
    int h = idx / (KHH * D);
    int s = g_hhidx[i];
    g_kcat[((size_t)h * KC + i) * D + d] = g_k[(size_t)s * HID + h * D + d];
    g_vcat[((size_t)h * KC + i) * D + d] = g_v[(size_t)s * HID + h * D + d];
}

// ---------------- fused attention over 716 concatenated keys (16 queries / block) ----------------
__global__ __launch_bounds__(256) void attn2_kernel() {
    extern __shared__ float sm[];
    float* Qs  = sm;                       // 16*64
    float* Ss  = sm + 16 * 64;             // 16*KCP
    float* KVs = sm + 16 * 64 + 16 * KCP;  // 64*68
    int h   = blockIdx.y;
    int q0  = blockIdx.x * 16;
    int tid = threadIdx.x;
    {
        int r = tid >> 4;
        int c = (tid & 15) << 2;
        *(float4*)&Qs[r * 64 + c] =
            *(const float4*)&g_q[(size_t)(q0 + r) * HID + h * D + c];
    }
    __syncthreads();
    const float* kbase = g_kcat + (size_t)h * KC * D;
    const float* vbase = g_vcat + (size_t)h * KC * D;

    // ---- scores: Ss[16][716] ----
    int kj  = tid & 63;
    int qi0 = (tid >> 6) * 4;
    for (int kt = 0; kt < KC; kt += 64) {
        int rows = min(64, KC - kt);
        for (int f = tid; f < rows * 16; f += 256) {
            int r = f >> 4;
            int c = (f & 15) << 2;
            *(float4*)&KVs[r * 68 + c] =
                *(const float4*)&kbase[(size_t)(kt + r) * D + c];
        }
        __syncthreads();
        if (kj < rows) {
            float a0 = 0.f, a1 = 0.f, a2 = 0.f, a3 = 0.f;
#pragma unroll
            for (int dd = 0; dd < 64; dd += 4) {
                float4 kv = *(float4*)&KVs[kj * 68 + dd];
                float4 q0v = *(float4*)&Qs[(qi0 + 0) * 64 + dd];
                float4 q1v = *(float4*)&Qs[(qi0 + 1) * 64 + dd];
                float4 q2v = *(float4*)&Qs[(qi0 + 2) * 64 + dd];
                float4 q3v = *(float4*)&Qs[(qi0 + 3) * 64 + dd];
                a0 += q0v.x * kv.x + q0v.y * kv.y + q0v.z * kv.z + q0v.w * kv.w;
                a1 += q1v.x * kv.x + q1v.y * kv.y + q1v.z * kv.z + q1v.w * kv.w;
                a2 += q2v.x * kv.x + q2v.y * kv.y + q2v.z * kv.z + q2v.w * kv.w;
                a3 += q3v.x * kv.x + q3v.y * kv.y + q3v.z * kv.z + q3v.w * kv.w;
            }
            Ss[(qi0 + 0) * KCP + kt + kj] = a0 * SCALE;
            Ss[(qi0 + 1) * KCP + kt + kj] = a1 * SCALE;
            Ss[(qi0 + 2) * KCP + kt + kj] = a2 * SCALE;
            Ss[(qi0 + 3) * KCP + kt + kj] = a3 * SCALE;
        }
        __syncthreads();
    }

    // ---- softmax rows (8 warps x 2 rows) ----
    int wid = tid >> 5, lane = tid & 31;
    for (int rr = 0; rr < 2; rr++) {
        int row = wid * 2 + rr;
        float* srow = Ss + row * KCP;
        float m = -1e30f;
        for (int j = lane; j < KC; j += 32) m = fmaxf(m, srow[j]);
#pragma unroll
        for (int o = 16; o; o >>= 1) m = fmaxf(m, __shfl_xor_sync(0xffffffffu, m, o));
        float z = 0.f;
        for (int j = lane; j < KC; j += 32) { float e = __expf(srow[j] - m); srow[j] = e; z += e; }
#pragma unroll
        for (int o = 16; o; o >>= 1) z += __shfl_xor_sync(0xffffffffu, z, o);
        float rzz = 1.0f / z;
        for (int j = lane; j < KC; j += 32) srow[j] *= rzz;
    }

    // ---- P @ V ----
    int d  = tid & 63;
    int qg = tid >> 6;  // owns rows qg, qg+4, qg+8, qg+12
    float acc0 = 0.f, acc1 = 0.f, acc2 = 0.f, acc3 = 0.f;
    for (int vt = 0; vt < KC; vt += 64) {
        int rows = min(64, KC - vt);
        __syncthreads();
        for (int f = tid; f < rows * 16; f += 256) {
            int r = f >> 4;
            int c = (f & 15) << 2;
            *(float4*)&KVs[r * 68 + c] =
                *(const float4*)&vbase[(size_t)(vt + r) * D + c];
        }
        __syncthreads();
        for (int r = 0; r < rows; r += 4) {
            float v0 = KVs[(r + 0) * 68 + d];
            float v1 = KVs[(r + 1) * 68 + d];
            float v2 = KVs[(r + 2) * 68 + d];
            float v3 = KVs[(r + 3) * 68 + d];
            float4 p0 = *(float4*)&Ss[(qg + 0) * KCP + vt + r];
            float4 p1 = *(float4*)&Ss[(qg + 4) * KCP + vt + r];
            float4 p2 = *(float4*)&Ss[(qg + 8) * KCP + vt + r];
            float4 p3 = *(float4*)&Ss[(qg + 12) * KCP + vt + r];
            acc0 += p0.x * v0 + p0.y * v1 + p0.z * v2 + p0.w * v3;
            acc1 += p1.x * v0 + p1.y * v1 + p1.z * v2 + p1.w * v3;
            acc2 += p2.x * v0 + p2.y * v1 + p2.z * v2 + p2.w * v3;
            acc3 += p3.x * v0 + p3.y * v1 + p3.z * v2 + p3.w * v3;
        }
    }
    g_ao[(size_t)(q0 + qg +  0) * HID + h * D + d] = acc0;
    g_ao[(size_t)(q0 + qg +  4) * HID + h * D + d] = acc1;
    g_ao[(size_t)(q0 + qg +  8) * HID + h * D + d] = acc2;
    g_ao[(size_t)(q0 + qg + 12) * HID + h * D + d] = acc3;
}

// ---------------- host ----------------
extern "C" void kernel_launch(void* const* d_in, const int* in_sizes, int n_in,
                              void* d_out, int out_size) {
    const float* x  = (const float*)d_in[0];
    const float* wq = (const float*)d_in[1];
    const float* wk = (const float*)d_in[2];
    const float* wv = (const float*)d_in[3];
    const float* wo = (const float*)d_in[4];
    float* out = (float*)d_out;

    static bool init_done = false;
    static void* ent_addr = nullptr;
    static void* infl_addr = nullptr;
    if (!init_done) {
        cudaFuncSetAttribute(attn2_kernel,
                             cudaFuncAttributeMaxDynamicSharedMemorySize,
                             (16 * 64 + 16 * KCP + 64 * 68) * sizeof(float));
        cudaGetSymbolAddress(&ent_addr, g_ent);
        cudaGetSymbolAddress(&infl_addr, g_infl);
        init_done = true;
    }

    cudaMemsetAsync(ent_addr, 0, H * S * sizeof(float));
    cudaMemsetAsync(infl_addr, 0, H * S * sizeof(float));
    qkv_kernel<<<dim3(8, 16, 3), 256>>>(x, wq, wk, wv);
    scores_kernel<<<dim3(32, 32, 16), 256>>>();
    combine_kernel<<<(H * S) / 8, 256>>>();
    stats_kernel<<<dim3(16, 16, 16), 256>>>();
    importance_kernel<<<8, 256>>>();
    topk_kernel<<<8, 256>>>();
    compress_kernel<<<dim3(16, 2), 256>>>();
    gather_kernel<<<(H * KHH * D + 255) / 256, 256>>>();
    attn2_kernel<<<dim3(S / 16, H), 256,
                   (16 * 64 + 16 * KCP + 64 * 68) * sizeof(float)>>>();
    out_kernel<<<dim3(8, 16), 256>>>(wo, out);
}

// round 4
// speedup vs baseline: 1.5171x; 1.1793x over previous
#include <cuda_runtime.h>

#define S     2048
#define H     16
#define D     64
#define HID   1024
#define KHH   204
#define LCOMP 512
#define KC    716     // KHH + LCOMP
#define KCPAD 768     // padded key count for attn2 chunking
#define SCALE 0.125f  // 1/sqrt(64)
#define NKT   16      // 128-wide k tiles per score row
#define LOG1EM8 -18.420680743952367f

// ---------------- device scratch (allocation-free; module globals) ----------------
__device__ float g_q[S * HID];
__device__ float g_k[S * HID];
__device__ float g_v[S * HID];
__device__ float g_ao[S * HID];
__device__ float g_scores[(size_t)H * S * S];   // raw scaled scores (256 MB)
__device__ float g_pm[H * S * NKT];             // per-tile row max
__device__ float g_pz[H * S * NKT];             // per-tile row sumexp
__device__ float g_rowM[H * S];
__device__ float g_rowZ[H * S];                 // 1/Z
__device__ float g_logZ[H * S];
__device__ float g_ent[H * S];                  // accumulates sum p*log(clip(p)) = -entropy
__device__ float g_maxa[H * S];
__device__ float g_infl[H * S];
__device__ float g_imp[S];
__device__ int   g_hhidx[KHH];
__device__ float g_kcat[(size_t)H * KCPAD * D];
__device__ float g_vcat[(size_t)H * KCPAD * D];

// ---------------- generic 128x128x8 SGEMM body (M=2048 rows, N=K=1024) ----------------
__device__ __forceinline__ void sgemm_body(const float* __restrict__ A,
                                           const float* __restrict__ B,
                                           float* __restrict__ C) {
    const int Kdim = 1024, N = 1024;
    __shared__ float As[8][128];
    __shared__ float Bs[8][128];
    int tid  = threadIdx.x;
    int crow = blockIdx.y * 128;
    int ccol = blockIdx.x * 128;
    int aRow = tid >> 1;
    int aCol = (tid & 1) * 4;
    int bRow = tid >> 5;
    int bCol = (tid & 31) * 4;
    int tRow = (tid >> 4) * 8;
    int tCol = (tid & 15) * 8;
    float acc[8][8];
#pragma unroll
    for (int i = 0; i < 8; i++)
#pragma unroll
        for (int j = 0; j < 8; j++) acc[i][j] = 0.0f;

    for (int k0 = 0; k0 < Kdim; k0 += 8) {
        float4 av = *(const float4*)&A[(size_t)(crow + aRow) * Kdim + k0 + aCol];
        As[aCol + 0][aRow] = av.x;
        As[aCol + 1][aRow] = av.y;
        As[aCol + 2][aRow] = av.z;
        As[aCol + 3][aRow] = av.w;
        *(float4*)&Bs[bRow][bCol] =
            *(const float4*)&B[(size_t)(k0 + bRow) * N + ccol + bCol];
        __syncthreads();
#pragma unroll
        for (int kk = 0; kk < 8; kk++) {
            float rm[8], rn[8];
            *(float4*)&rm[0] = *(float4*)&As[kk][tRow];
            *(float4*)&rm[4] = *(float4*)&As[kk][tRow + 4];
            *(float4*)&rn[0] = *(float4*)&Bs[kk][tCol];
            *(float4*)&rn[4] = *(float4*)&Bs[kk][tCol + 4];
#pragma unroll
            for (int i = 0; i < 8; i++)
#pragma unroll
                for (int j = 0; j < 8; j++) acc[i][j] += rm[i] * rn[j];
        }
        __syncthreads();
    }
#pragma unroll
    for (int i = 0; i < 8; i++)
#pragma unroll
        for (int j = 0; j < 8; j += 4) {
            float4 o = make_float4(acc[i][j], acc[i][j + 1], acc[i][j + 2], acc[i][j + 3]);
            *(float4*)&C[(size_t)(crow + tRow + i) * N + ccol + tCol + j] = o;
        }
}

__global__ __launch_bounds__(256) void qkv_kernel(const float* __restrict__ x,
                                                  const float* __restrict__ wq,
                                                  const float* __restrict__ wk,
                                                  const float* __restrict__ wv) {
    const float* B = blockIdx.z == 0 ? wq : (blockIdx.z == 1 ? wk : wv);
    float* C = blockIdx.z == 0 ? g_q : (blockIdx.z == 1 ? g_k : g_v);
    sgemm_body(x, B, C);
}

__global__ __launch_bounds__(256) void out_kernel(const float* __restrict__ wo,
                                                  float* __restrict__ out) {
    sgemm_body(g_ao, wo, out);
}

// ---------------- scores GEMM 128x128 tiles + per-tile row max / sumexp partials ----------------
__global__ __launch_bounds__(256) void scores_kernel() {
    int h  = blockIdx.z;
    int q0 = blockIdx.y * 128;
    int k0 = blockIdx.x * 128;
    __shared__ float As[8][132];  // Q^T chunk [kk][q]
    __shared__ float Bs[8][132];  // K^T chunk [kk][k]
    int tid  = threadIdx.x;
    int aRow = tid >> 1;          // 0..127
    int aCol = (tid & 1) * 4;     // 0 or 4
    int tRow = (tid >> 4) * 8;
    int tCol = (tid & 15) * 8;
    const float* qb = g_q + h * D;
    const float* kb = g_k + h * D;
    float acc[8][8];
#pragma unroll
    for (int i = 0; i < 8; i++)
#pragma unroll
        for (int j = 0; j < 8; j++) acc[i][j] = 0.0f;

    for (int c0 = 0; c0 < D; c0 += 8) {
        float4 qv = *(const float4*)&qb[(size_t)(q0 + aRow) * HID + c0 + aCol];
        As[aCol + 0][aRow] = qv.x;
        As[aCol + 1][aRow] = qv.y;
        As[aCol + 2][aRow] = qv.z;
        As[aCol + 3][aRow] = qv.w;
        float4 kv = *(const float4*)&kb[(size_t)(k0 + aRow) * HID + c0 + aCol];
        Bs[aCol + 0][aRow] = kv.x;
        Bs[aCol + 1][aRow] = kv.y;
        Bs[aCol + 2][aRow] = kv.z;
        Bs[aCol + 3][aRow] = kv.w;
        __syncthreads();
#pragma unroll
        for (int kk = 0; kk < 8; kk++) {
            float rm[8], rn[8];
            *(float4*)&rm[0] = *(float4*)&As[kk][tRow];
            *(float4*)&rm[4] = *(float4*)&As[kk][tRow + 4];
            *(float4*)&rn[0] = *(float4*)&Bs[kk][tCol];
            *(float4*)&rn[4] = *(float4*)&Bs[kk][tCol + 4];
#pragma unroll
            for (int i = 0; i < 8; i++)
#pragma unroll
                for (int j = 0; j < 8; j++) acc[i][j] += rm[i] * rn[j];
        }
        __syncthreads();
    }
#pragma unroll
    for (int i = 0; i < 8; i++)
#pragma unroll
        for (int j = 0; j < 8; j++) acc[i][j] *= SCALE;

    float* sc = g_scores + (size_t)h * S * S;
#pragma unroll
    for (int i = 0; i < 8; i++) {
        *(float4*)&sc[(size_t)(q0 + tRow + i) * S + k0 + tCol] =
            make_float4(acc[i][0], acc[i][1], acc[i][2], acc[i][3]);
        *(float4*)&sc[(size_t)(q0 + tRow + i) * S + k0 + tCol + 4] =
            make_float4(acc[i][4], acc[i][5], acc[i][6], acc[i][7]);
    }

    // per-tile row stats via 16-lane shuffles (threads tid&15 own one row-group)
#pragma unroll
    for (int i = 0; i < 8; i++) {
        float m = acc[i][0];
#pragma unroll
        for (int j = 1; j < 8; j++) m = fmaxf(m, acc[i][j]);
#pragma unroll
        for (int o = 1; o < 16; o <<= 1) m = fmaxf(m, __shfl_xor_sync(0xffffffffu, m, o));
        float z = 0.f;
#pragma unroll
        for (int j = 0; j < 8; j++) z += __expf(acc[i][j] - m);
#pragma unroll
        for (int o = 1; o < 16; o <<= 1) z += __shfl_xor_sync(0xffffffffu, z, o);
        if ((tid & 15) == 0) {
            size_t idx = (size_t)(h * S + q0 + tRow + i) * NKT + blockIdx.x;
            g_pm[idx] = m;
            g_pz[idx] = z;
        }
    }
}

// ---------------- combine partials: m, 1/Z, logZ, max_attn ----------------
__global__ __launch_bounds__(256) void combine_kernel() {
    int row = blockIdx.x * 16 + (threadIdx.x >> 4);  // 0..H*S-1
    int l   = threadIdx.x & 15;
    float pm = g_pm[(size_t)row * NKT + l];
    float pz = g_pz[(size_t)row * NKT + l];
    float m = pm;
#pragma unroll
    for (int o = 1; o < 16; o <<= 1) m = fmaxf(m, __shfl_xor_sync(0xffffffffu, m, o));
    float z = __expf(pm - m) * pz;
#pragma unroll
    for (int o = 1; o < 16; o <<= 1) z += __shfl_xor_sync(0xffffffffu, z, o);
    if (l == 0) {
        float rz = 1.0f / z;
        g_rowM[row] = m;
        g_rowZ[row] = rz;
        g_logZ[row] = __logf(z);
        g_maxa[row] = rz;
    }
}

// ---------------- fused entropy + influence: single pass over scores ----------------
__global__ __launch_bounds__(256) void stats_kernel() {
    int h  = blockIdx.z;
    int q0 = blockIdx.y * 128;
    int k0 = blockIdx.x * 128;
    int tid = threadIdx.x;
    int wid = tid >> 5, lane = tid & 31;
    __shared__ float wcol[8][128];

    const float* sc = g_scores + (size_t)h * S * S;
    float c0 = 0.f, c1 = 0.f, c2 = 0.f, c3 = 0.f;

#pragma unroll 4
    for (int r = 0; r < 16; r++) {
        int row = q0 + wid * 16 + r;
        float m  = g_rowM[h * S + row];
        float rz = g_rowZ[h * S + row];
        float lz = g_logZ[h * S + row];
        float4 v = *(const float4*)&sc[(size_t)row * S + k0 + lane * 4];
        float s0 = v.x - m, s1 = v.y - m, s2 = v.z - m, s3 = v.w - m;
        float p0 = __expf(s0) * rz, p1 = __expf(s1) * rz;
        float p2 = __expf(s2) * rz, p3 = __expf(s3) * rz;
        c0 += p0; c1 += p1; c2 += p2; c3 += p3;
        float t0 = p0 * ((p0 >= 1e-8f) ? (s0 - lz) : LOG1EM8);
        float t1 = p1 * ((p1 >= 1e-8f) ? (s1 - lz) : LOG1EM8);
        float t2 = p2 * ((p2 >= 1e-8f) ? (s2 - lz) : LOG1EM8);
        float t3 = p3 * ((p3 >= 1e-8f) ? (s3 - lz) : LOG1EM8);
        float e = t0 + t1 + t2 + t3;
#pragma unroll
        for (int o = 16; o; o >>= 1) e += __shfl_xor_sync(0xffffffffu, e, o);
        if (lane == 0) atomicAdd(&g_ent[h * S + row], e);
    }
    *(float4*)&wcol[wid][lane * 4] = make_float4(c0, c1, c2, c3);
    __syncthreads();
    if (tid < 128) {
        float s = 0.f;
#pragma unroll
        for (int w = 0; w < 8; w++) s += wcol[w][tid];
        atomicAdd(&g_infl[h * S + k0 + tid], s);
    }
}

__global__ void importance_kernel() {
    int s = blockIdx.x * 256 + threadIdx.x;
    if (s >= S) return;
    float a = 0.f;
    for (int h = 0; h < H; h++)
        a += 0.4f * g_ent[h * S + s]   // g_ent = sum p log p = -entropy
           + 0.3f * g_maxa[h * S + s] + 0.3f * g_infl[h * S + s];
    g_imp[s] = a * (1.0f / H);
}

// ---------------- top-204 via rank counting (attention is permutation invariant over keys) ----------------
__global__ void topk_kernel() {
    int i = blockIdx.x * 256 + threadIdx.x;
    if (i >= S) return;
    float vi = g_imp[i];
    int r = 0;
    for (int j = 0; j < S; j++) {
        float vj = g_imp[j];
        r += (vj > vi) || (vj == vi && j < i);
    }
    if (r < KHH) g_hhidx[r] = i;
}

// ---------------- norm-softmax-weighted 4:1 compression of K/V ----------------
__global__ __launch_bounds__(256) void compress_kernel() {
    int h = blockIdx.x;
    int which = blockIdx.y;
    const float* src = which ? g_v : g_k;
    float* dst = (which ? g_vcat : g_kcat) + ((size_t)h * KCPAD + KHH) * D;
    __shared__ float w[S];
    __shared__ float gs[LCOMP];
    __shared__ float red[256];
    int tid = threadIdx.x;

    for (int s = tid; s < S; s += 256) {
        const float* rp = src + (size_t)s * HID + h * D;
        float a = 0.f;
#pragma unroll
        for (int dd = 0; dd < 64; dd += 4) {
            float4 xv = *(const float4*)&rp[dd];
            a += xv.x * xv.x + xv.y * xv.y + xv.z * xv.z + xv.w * xv.w;
        }
        w[s] = sqrtf(a);
    }
    __syncthreads();
    float lm = -1e30f;
    for (int s = tid; s < S; s += 256) lm = fmaxf(lm, w[s]);
    red[tid] = lm; __syncthreads();
    for (int o = 128; o; o >>= 1) { if (tid < o) red[tid] = fmaxf(red[tid], red[tid + o]); __syncthreads(); }
    float m = red[0]; __syncthreads();
    float lz = 0.f;
    for (int s = tid; s < S; s += 256) { float e = __expf(w[s] - m); w[s] = e; lz += e; }
    red[tid] = lz; __syncthreads();
    for (int o = 128; o; o >>= 1) { if (tid < o) red[tid] += red[tid + o]; __syncthreads(); }
    float rz = 1.0f / red[0]; __syncthreads();
    for (int s = tid; s < S; s += 256) w[s] *= rz;
    __syncthreads();
    for (int l = tid; l < LCOMP; l += 256)
        gs[l] = w[4 * l] + w[4 * l + 1] + w[4 * l + 2] + w[4 * l + 3];
    __syncthreads();
    for (int idx = tid; idx < LCOMP * D; idx += 256) {
        int l  = idx >> 6;
        int dd = idx & 63;
        const float* rp = src + (size_t)(4 * l) * HID + h * D + dd;
        float num = w[4 * l] * rp[0] + w[4 * l + 1] * rp[HID] +
                    w[4 * l + 2] * rp[2 * HID] + w[4 * l + 3] * rp[3 * HID];
        dst[(size_t)l * D + dd] = num / (gs[l] + 1e-8f);
    }
}

__global__ void gather_kernel() {
    int idx = blockIdx.x * 256 + threadIdx.x;
    if (idx >= H * KHH * D) return;
    int d = idx & 63;
    int i = (idx >> 6) % KHH;
    int h = idx / (KHH * D);
    int s = g_hhidx[i];
    g_kcat[((size_t)h * KCPAD + i) * D + d] = g_k[(size_t)s * HID + h * D + d];
    g_vcat[((size_t)h * KCPAD + i) * D + d] = g_v[(size_t)s * HID + h * D + d];
}

// ---------------- flash-style attention over 716(+pad) keys: 128 queries / block ----------------
__global__ __launch_bounds__(256) void attn2_kernel() {
    extern __shared__ float sm[];
    float* Qt  = sm;                       // [64][132]  Q^T  (d-major)
    float* KVs = sm + 64 * 132;            // [64][68]   K^T then V
    float* Pt  = sm + 64 * 132 + 64 * 68;  // [64][132]  P^T  (k-major)
    int h   = blockIdx.y;
    int q0  = blockIdx.x * 128;
    int tid = threadIdx.x;
    int tRow = (tid >> 4) * 8;   // q rows
    int tc4  = (tid & 15) * 4;   // k cols / d cols

    for (int f = tid; f < 128 * 16; f += 256) {
        int r = f >> 4, c = (f & 15) << 2;
        float4 qv = *(const float4*)&g_q[(size_t)(q0 + r) * HID + h * D + c];
        Qt[(c + 0) * 132 + r] = qv.x; Qt[(c + 1) * 132 + r] = qv.y;
        Qt[(c + 2) * 132 + r] = qv.z; Qt[(c + 3) * 132 + r] = qv.w;
    }
    const float* kbase = g_kcat + (size_t)h * KCPAD * D;
    const float* vbase = g_vcat + (size_t)h * KCPAD * D;

    float oc[8][4];
    float m_run[8], z_run[8];
#pragma unroll
    for (int i = 0; i < 8; i++) {
        m_run[i] = -1e30f; z_run[i] = 0.f;
#pragma unroll
        for (int j = 0; j < 4; j++) oc[i][j] = 0.f;
    }

    for (int kt = 0; kt < KCPAD; kt += 64) {
        __syncthreads();
        // K chunk transposed [d][k]
        for (int f = tid; f < 64 * 16; f += 256) {
            int kr = f >> 4, c = (f & 15) << 2;
            float4 kv = *(const float4*)&kbase[(size_t)(kt + kr) * D + c];
            KVs[(c + 0) * 68 + kr] = kv.x; KVs[(c + 1) * 68 + kr] = kv.y;
            KVs[(c + 2) * 68 + kr] = kv.z; KVs[(c + 3) * 68 + kr] = kv.w;
        }
        __syncthreads();
        float s[8][4];
#pragma unroll
        for (int i = 0; i < 8; i++)
#pragma unroll
            for (int j = 0; j < 4; j++) s[i][j] = 0.f;
#pragma unroll 8
        for (int dd = 0; dd < 64; dd++) {
            float rm[8], rn[4];
            *(float4*)&rm[0] = *(float4*)&Qt[dd * 132 + tRow];
            *(float4*)&rm[4] = *(float4*)&Qt[dd * 132 + tRow + 4];
            *(float4*)&rn[0] = *(float4*)&KVs[dd * 68 + tc4];
#pragma unroll
            for (int i = 0; i < 8; i++)
#pragma unroll
                for (int j = 0; j < 4; j++) s[i][j] += rm[i] * rn[j];
        }
        bool mk[4];
#pragma unroll
        for (int j = 0; j < 4; j++) mk[j] = (kt + tc4 + j) >= KC;
#pragma unroll
        for (int i = 0; i < 8; i++) {
#pragma unroll
            for (int j = 0; j < 4; j++)
                s[i][j] = mk[j] ? -1e30f : s[i][j] * SCALE;
            float cm = fmaxf(fmaxf(s[i][0], s[i][1]), fmaxf(s[i][2], s[i][3]));
#pragma unroll
            for (int o = 1; o < 16; o <<= 1) cm = fmaxf(cm, __shfl_xor_sync(0xffffffffu, cm, o));
            float mn  = fmaxf(m_run[i], cm);
            float fac = __expf(m_run[i] - mn);
            float p0 = __expf(s[i][0] - mn), p1 = __expf(s[i][1] - mn);
            float p2 = __expf(s[i][2] - mn), p3 = __expf(s[i][3] - mn);
            float zs = p0 + p1 + p2 + p3;
#pragma unroll
            for (int o = 1; o < 16; o <<= 1) zs += __shfl_xor_sync(0xffffffffu, zs, o);
            z_run[i] = z_run[i] * fac + zs;
            m_run[i] = mn;
#pragma unroll
            for (int j = 0; j < 4; j++) oc[i][j] *= fac;
            Pt[(tc4 + 0) * 132 + tRow + i] = p0;
            Pt[(tc4 + 1) * 132 + tRow + i] = p1;
            Pt[(tc4 + 2) * 132 + tRow + i] = p2;
            Pt[(tc4 + 3) * 132 + tRow + i] = p3;
        }
        __syncthreads();
        // V chunk natural [k][d]
        for (int f = tid; f < 64 * 16; f += 256) {
            int kr = f >> 4, c = (f & 15) << 2;
            *(float4*)&KVs[kr * 68 + c] =
                *(const float4*)&vbase[(size_t)(kt + kr) * D + c];
        }
        __syncthreads();
#pragma unroll 8
        for (int kk = 0; kk < 64; kk++) {
            float rm[8], rn[4];
            *(float4*)&rm[0] = *(float4*)&Pt[kk * 132 + tRow];
            *(float4*)&rm[4] = *(float4*)&Pt[kk * 132 + tRow + 4];
            *(float4*)&rn[0] = *(float4*)&KVs[kk * 68 + tc4];
#pragma unroll
            for (int i = 0; i < 8; i++)
#pragma unroll
                for (int j = 0; j < 4; j++) oc[i][j] += rm[i] * rn[j];
        }
    }
#pragma unroll
    for (int i = 0; i < 8; i++) {
        float rz = 1.0f / z_run[i];
        *(float4*)&g_ao[(size_t)(q0 + tRow + i) * HID + h * D + tc4] =
            make_float4(oc[i][0] * rz, oc[i][1] * rz, oc[i][2] * rz, oc[i][3] * rz);
    }
}

// ---------------- host ----------------
#define ATTN2_SMEM ((64 * 132 + 64 * 68 + 64 * 132) * (int)sizeof(float))

extern "C" void kernel_launch(void* const* d_in, const int* in_sizes, int n_in,
                              void* d_out, int out_size) {
    const float* x  = (const float*)d_in[0];
    const float* wq = (const float*)d_in[1];
    const float* wk = (const float*)d_in[2];
    const float* wv = (const float*)d_in[3];
    const float* wo = (const float*)d_in[4];
    float* out = (float*)d_out;

    static bool init_done = false;
    static void* ent_addr = nullptr;
    static void* infl_addr = nullptr;
    static void* kcat_addr = nullptr;
    static void* vcat_addr = nullptr;
    if (!init_done) {
        cudaFuncSetAttribute(attn2_kernel,
                             cudaFuncAttributeMaxDynamicSharedMemorySize, ATTN2_SMEM);
        cudaGetSymbolAddress(&ent_addr, g_ent);
        cudaGetSymbolAddress(&infl_addr, g_infl);
        cudaGetSymbolAddress(&kcat_addr, g_kcat);
        cudaGetSymbolAddress(&vcat_addr, g_vcat);
        init_done = true;
    }

    cudaMemsetAsync(ent_addr, 0, H * S * sizeof(float));
    cudaMemsetAsync(infl_addr, 0, H * S * sizeof(float));
    cudaMemsetAsync(kcat_addr, 0, (size_t)H * KCPAD * D * sizeof(float));
    cudaMemsetAsync(vcat_addr, 0, (size_t)H * KCPAD * D * sizeof(float));

    qkv_kernel<<<dim3(8, 16, 3), 256>>>(x, wq, wk, wv);
    scores_kernel<<<dim3(16, 16, 16), 256>>>();
    combine_kernel<<<(H * S) / 16, 256>>>();
    stats_kernel<<<dim3(16, 16, 16), 256>>>();
    importance_kernel<<<8, 256>>>();
    topk_kernel<<<8, 256>>>();
    compress_kernel<<<dim3(16, 2), 256>>>();
    gather_kernel<<<(H * KHH * D + 255) / 256, 256>>>();
    attn2_kernel<<<dim3(S / 128, H), 256, ATTN2_SMEM>>>();
    out_kernel<<<dim3(8, 16), 256>>>(wo, out);
}